// round 1
// baseline (speedup 1.0000x reference)
#include <cuda_runtime.h>
#include <math.h>

// Problem constants (B,H,L,D fixed by the dataset)
#define CB    2
#define CH    16
#define CL    4096
#define CD    128
#define CWIN  2048
#define CSINK 4

#define BM    64          // queries per block
#define BN    64          // keys per tile
#define NTH   256         // 16x16 thread grid
#define KSTRIDE 132       // padded K row stride (floats) to break bank conflicts

// smem layout (floats): Qs[BM*CD] | Ks[BN*KSTRIDE] | Vs[BN*CD] | Ps[BM*BN]
#define SMEM_FLOATS (BM*CD + BN*KSTRIDE + BN*CD + BM*BN)
#define SMEM_BYTES  (SMEM_FLOATS * 4)

__device__ __forceinline__ float red_max16(float v) {
    #pragma unroll
    for (int off = 8; off > 0; off >>= 1)
        v = fmaxf(v, __shfl_xor_sync(0xffffffffu, v, off, 16));
    return v;
}
__device__ __forceinline__ float red_sum16(float v) {
    #pragma unroll
    for (int off = 8; off > 0; off >>= 1)
        v += __shfl_xor_sync(0xffffffffu, v, off, 16);
    return v;
}

__global__ __launch_bounds__(NTH, 2)
void swa_ffma_kernel(const float* __restrict__ Q, const float* __restrict__ K,
                     const float* __restrict__ V, float* __restrict__ O) {
    extern __shared__ float sm[];
    float* Qs = sm;                    // BM x CD       (stride 128)
    float* Ks = Qs + BM * CD;          // BN x KSTRIDE  (stride 132)
    float* Vs = Ks + BN * KSTRIDE;     // BN x CD       (stride 128)
    float* Ps = Vs + BN * CD;          // BM x BN       (stride 64)

    const int bh  = blockIdx.y;
    const int q0  = blockIdx.x * BM;
    const int tid = threadIdx.x;
    const int tx  = tid & 15;          // k-col group / d-col group
    const int ty  = tid >> 4;          // q-row group

    const float scale = 0.08838834764831843f;   // 1/sqrt(128)

    const size_t base = (size_t)bh * CL * CD;
    const float* qb = Q + base + (size_t)q0 * CD;
    const float* kb = K + base;
    const float* vb = V + base;
    float*       ob = O + base + (size_t)q0 * CD;

    // ---- load Q tile (coalesced float4; layout identical to gmem) ----
    #pragma unroll
    for (int e = tid; e < BM * CD / 4; e += NTH)
        reinterpret_cast<float4*>(Qs)[e] = reinterpret_cast<const float4*>(qb)[e];

    // ---- per-thread softmax state + output accumulators ----
    float m_i[4], l_i[4], o[4][8];
    #pragma unroll
    for (int i = 0; i < 4; i++) {
        m_i[i] = -INFINITY; l_i[i] = 0.f;
        #pragma unroll
        for (int jj = 0; jj < 8; jj++) o[i][jj] = 0.f;
    }

    // ---- k-tile schedule: sink tile 0 (if disjoint) then window band ----
    const int kt_hi = q0 >> 6;
    const int kt_lo = (q0 >= CWIN) ? ((q0 - CWIN + 1) >> 6) : 0;
    const int nt = kt_hi - kt_lo + 1 + (kt_lo > 0 ? 1 : 0);

    for (int t = 0; t < nt; t++) {
        const int kt = (kt_lo > 0) ? (t == 0 ? 0 : kt_lo + t - 1) : t;
        const int k0 = kt * BN;

        __syncthreads();   // previous iter done reading Ks/Vs/Ps
        // ---- load K (padded) and V tiles ----
        #pragma unroll
        for (int e = tid; e < BN * CD / 4; e += NTH) {
            const int row = e >> 5;            // 32 float4 per row
            const int c   = (e & 31) << 2;
            float4 kk = reinterpret_cast<const float4*>(kb + (size_t)k0 * CD)[e];
            *reinterpret_cast<float4*>(&Ks[row * KSTRIDE + c]) = kk;
            reinterpret_cast<float4*>(Vs)[e] =
                reinterpret_cast<const float4*>(vb + (size_t)k0 * CD)[e];
        }
        __syncthreads();

        // ---- S = Q K^T for this thread's 4x4 micro-tile ----
        float s[4][4];
        #pragma unroll
        for (int i = 0; i < 4; i++)
            #pragma unroll
            for (int j = 0; j < 4; j++) s[i][j] = 0.f;

        for (int d = 0; d < CD; d += 4) {
            float4 qv[4], kv[4];
            #pragma unroll
            for (int i = 0; i < 4; i++)
                qv[i] = *reinterpret_cast<const float4*>(&Qs[(ty + 16 * i) * CD + d]);
            #pragma unroll
            for (int j = 0; j < 4; j++)
                kv[j] = *reinterpret_cast<const float4*>(&Ks[(tx + 16 * j) * KSTRIDE + d]);
            #pragma unroll
            for (int i = 0; i < 4; i++)
                #pragma unroll
                for (int j = 0; j < 4; j++) {
                    s[i][j] = fmaf(qv[i].x, kv[j].x, s[i][j]);
                    s[i][j] = fmaf(qv[i].y, kv[j].y, s[i][j]);
                    s[i][j] = fmaf(qv[i].z, kv[j].z, s[i][j]);
                    s[i][j] = fmaf(qv[i].w, kv[j].w, s[i][j]);
                }
        }

        // ---- mask + scale ----
        #pragma unroll
        for (int i = 0; i < 4; i++) {
            const int qp = q0 + ty + 16 * i;
            #pragma unroll
            for (int j = 0; j < 4; j++) {
                const int kp = k0 + tx + 16 * j;
                const bool ok = (kp <= qp) && ((kp + CWIN > qp) || (kp < CSINK));
                s[i][j] = ok ? s[i][j] * scale : -INFINITY;
            }
        }

        // ---- online softmax update (per q-row, reduced over 16 tx lanes) ----
        #pragma unroll
        for (int i = 0; i < 4; i++) {
            float mx = fmaxf(fmaxf(s[i][0], s[i][1]), fmaxf(s[i][2], s[i][3]));
            mx = red_max16(mx);
            const float mnew  = fmaxf(m_i[i], mx);
            const float alpha = __expf(m_i[i] - mnew);   // exp(-inf - finite) = 0
            float rs = 0.f;
            #pragma unroll
            for (int j = 0; j < 4; j++) {
                const float p = __expf(s[i][j] - mnew);  // masked -> exp(-inf) = 0
                s[i][j] = p;
                rs += p;
            }
            rs = red_sum16(rs);
            l_i[i] = l_i[i] * alpha + rs;
            m_i[i] = mnew;
            #pragma unroll
            for (int jj = 0; jj < 8; jj++) o[i][jj] *= alpha;
            #pragma unroll
            for (int j = 0; j < 4; j++)
                Ps[(ty + 16 * i) * BN + tx + 16 * j] = s[i][j];
        }
        __syncthreads();

        // ---- O += P V ----
        #pragma unroll 4
        for (int kk = 0; kk < BN; kk++) {
            float pk[4], vv[8];
            #pragma unroll
            for (int i = 0; i < 4; i++) pk[i] = Ps[(ty + 16 * i) * BN + kk];
            #pragma unroll
            for (int jj = 0; jj < 8; jj++) vv[jj] = Vs[kk * CD + tx + 16 * jj];
            #pragma unroll
            for (int i = 0; i < 4; i++)
                #pragma unroll
                for (int jj = 0; jj < 8; jj++)
                    o[i][jj] = fmaf(pk[i], vv[jj], o[i][jj]);
        }
    }

    // ---- epilogue: normalize and store (coalesced: consecutive tx -> consecutive d) ----
    #pragma unroll
    for (int i = 0; i < 4; i++) {
        const float inv = 1.f / l_i[i];
        const int row = ty + 16 * i;
        #pragma unroll
        for (int jj = 0; jj < 8; jj++)
            ob[(size_t)row * CD + tx + 16 * jj] = o[i][jj] * inv;
    }
}

extern "C" void kernel_launch(void* const* d_in, const int* in_sizes, int n_in,
                              void* d_out, int out_size) {
    const float* q = (const float*)d_in[0];
    const float* k = (const float*)d_in[1];
    const float* v = (const float*)d_in[2];
    float* out = (float*)d_out;

    cudaFuncSetAttribute(swa_ffma_kernel,
                         cudaFuncAttributeMaxDynamicSharedMemorySize, SMEM_BYTES);

    dim3 grid(CL / BM, CB * CH);
    swa_ffma_kernel<<<grid, NTH, SMEM_BYTES>>>(q, k, v, out);
}

// round 3
// speedup vs baseline: 1.8042x; 1.8042x over previous
#include <cuda_runtime.h>
#include <math.h>
#include <stdint.h>

// Problem constants
#define CB 2
#define CH 16
#define CL 4096
#define CD 128
#define CWIN 2048
#define CSINK 4

#define BM 64
#define BN 64
#define NTH 128          // 4 warps; warp w owns q-rows [16w, 16w+16)
#define QSTR 132         // A-frag loads: bank = 4g+tr  (conflict-free)
#define KSTR 132         // B-frag loads: bank = 4g+tr  (conflict-free)
#define VSTR 136         // PV B-frag:    bank = 8tr+g  (conflict-free)
#define PSTR 68          // P A-frag:     bank = 4g+tr  (conflict-free)

#define SMEM_FLOATS (BM*QSTR + BN*KSTR + BN*VSTR + 4*16*PSTR)
#define SMEM_BYTES  (SMEM_FLOATS * 4)

__device__ __forceinline__ uint32_t f2tf32(float x) {
    uint32_t r;
    asm("cvt.rna.tf32.f32 %0, %1;" : "=r"(r) : "f"(x));
    return r;
}

__device__ __forceinline__ void mma_tf32(float c[4],
                                         uint32_t a0, uint32_t a1, uint32_t a2, uint32_t a3,
                                         uint32_t b0, uint32_t b1) {
    asm volatile(
        "mma.sync.aligned.m16n8k8.row.col.f32.tf32.tf32.f32 "
        "{%0,%1,%2,%3}, {%4,%5,%6,%7}, {%8,%9}, {%0,%1,%2,%3};"
        : "+f"(c[0]), "+f"(c[1]), "+f"(c[2]), "+f"(c[3])
        : "r"(a0), "r"(a1), "r"(a2), "r"(a3), "r"(b0), "r"(b1));
}

__global__ __launch_bounds__(NTH, 1)
void swa_tf32_kernel(const float* __restrict__ Q, const float* __restrict__ K,
                     const float* __restrict__ V, float* __restrict__ O) {
    extern __shared__ float sm[];
    float* Qs = sm;                       // BM x QSTR
    float* Ks = Qs + BM * QSTR;           // BN x KSTR
    float* Vs = Ks + BN * KSTR;           // BN x VSTR
    float* Ps = Vs + BN * VSTR;           // 4 warps x 16 x PSTR

    const int bh  = blockIdx.y;
    const int q0  = blockIdx.x * BM;
    const int tid = threadIdx.x;
    const int wid = tid >> 5;
    const int lane = tid & 31;
    const int g   = lane >> 2;            // groupID (0..7)
    const int tr  = lane & 3;             // thread-in-group (0..3)
    const float scale = 0.08838834764831843f;   // 1/sqrt(128)

    const size_t base = (size_t)bh * CL * CD;
    const float* qb = Q + base + (size_t)q0 * CD;
    const float* kb = K + base;
    const float* vb = V + base;
    float*       ob = O + base + (size_t)q0 * CD;

    // ---- load Q tile (cvt to tf32 bits once) ----
    for (int e = tid; e < BM * CD / 4; e += NTH) {
        const int r = e >> 5, c = (e & 31) << 2;
        float4 qv = reinterpret_cast<const float4*>(qb)[e];
        float* dst = &Qs[r * QSTR + c];
        dst[0] = __uint_as_float(f2tf32(qv.x));
        dst[1] = __uint_as_float(f2tf32(qv.y));
        dst[2] = __uint_as_float(f2tf32(qv.z));
        dst[3] = __uint_as_float(f2tf32(qv.w));
    }

    // ---- per-thread state: rows (qrow) and (qrow+8) of this warp's 16 rows ----
    float m0 = -INFINITY, m1 = -INFINITY, l0 = 0.f, l1 = 0.f;
    float o[16][4];
    #pragma unroll
    for (int nt = 0; nt < 16; nt++) {
        o[nt][0] = 0.f; o[nt][1] = 0.f; o[nt][2] = 0.f; o[nt][3] = 0.f;
    }

    float* Psw = Ps + wid * 16 * PSTR;
    const int qrow = wid * 16 + g;
    const int qp0 = q0 + qrow, qp1 = qp0 + 8;

    // ---- k-tile schedule: sink tile 0 (if disjoint) then window band ----
    const int kt_hi = q0 >> 6;
    const int kt_lo = (q0 >= CWIN) ? ((q0 - CWIN + 1) >> 6) : 0;
    const int ntiles = kt_hi - kt_lo + 1 + (kt_lo > 0 ? 1 : 0);

    for (int t = 0; t < ntiles; t++) {
        const int kt = (kt_lo > 0) ? (t == 0 ? 0 : kt_lo + t - 1) : t;
        const int k0 = kt * BN;

        __syncthreads();   // previous iter done with Ks/Vs (and Ps)
        // ---- load K, V tiles (cvt to tf32 bits) ----
        for (int e = tid; e < BN * CD / 4; e += NTH) {
            const int r = e >> 5, c = (e & 31) << 2;
            float4 kk = reinterpret_cast<const float4*>(kb + (size_t)k0 * CD)[e];
            float4 vv = reinterpret_cast<const float4*>(vb + (size_t)k0 * CD)[e];
            float* kd = &Ks[r * KSTR + c];
            kd[0] = __uint_as_float(f2tf32(kk.x));
            kd[1] = __uint_as_float(f2tf32(kk.y));
            kd[2] = __uint_as_float(f2tf32(kk.z));
            kd[3] = __uint_as_float(f2tf32(kk.w));
            float* vd = &Vs[r * VSTR + c];
            vd[0] = __uint_as_float(f2tf32(vv.x));
            vd[1] = __uint_as_float(f2tf32(vv.y));
            vd[2] = __uint_as_float(f2tf32(vv.z));
            vd[3] = __uint_as_float(f2tf32(vv.w));
        }
        __syncthreads();

        // ---- S = Q K^T : 16 k-chunks x 8 n-tiles of m16n8k8 ----
        float s[8][4];
        #pragma unroll
        for (int nt = 0; nt < 8; nt++) {
            s[nt][0] = 0.f; s[nt][1] = 0.f; s[nt][2] = 0.f; s[nt][3] = 0.f;
        }
        #pragma unroll
        for (int kc = 0; kc < 16; kc++) {
            const int d0 = kc * 8;
            uint32_t a0 = __float_as_uint(Qs[qrow * QSTR + d0 + tr]);
            uint32_t a1 = __float_as_uint(Qs[(qrow + 8) * QSTR + d0 + tr]);
            uint32_t a2 = __float_as_uint(Qs[qrow * QSTR + d0 + tr + 4]);
            uint32_t a3 = __float_as_uint(Qs[(qrow + 8) * QSTR + d0 + tr + 4]);
            #pragma unroll
            for (int nt = 0; nt < 8; nt++) {
                uint32_t b0 = __float_as_uint(Ks[(nt * 8 + g) * KSTR + d0 + tr]);
                uint32_t b1 = __float_as_uint(Ks[(nt * 8 + g) * KSTR + d0 + tr + 4]);
                mma_tf32(s[nt], a0, a1, a2, a3, b0, b1);
            }
        }

        // ---- mask + scale ----
        #pragma unroll
        for (int nt = 0; nt < 8; nt++) {
            const int kpa = k0 + nt * 8 + 2 * tr;
            const int kpb = kpa + 1;
            const bool sa = kpa < CSINK, sb = kpb < CSINK;
            const bool ok00 = (kpa <= qp0) && ((kpa + CWIN > qp0) || sa);
            const bool ok01 = (kpb <= qp0) && ((kpb + CWIN > qp0) || sb);
            const bool ok10 = (kpa <= qp1) && ((kpa + CWIN > qp1) || sa);
            const bool ok11 = (kpb <= qp1) && ((kpb + CWIN > qp1) || sb);
            s[nt][0] = ok00 ? s[nt][0] * scale : -INFINITY;
            s[nt][1] = ok01 ? s[nt][1] * scale : -INFINITY;
            s[nt][2] = ok10 ? s[nt][2] * scale : -INFINITY;
            s[nt][3] = ok11 ? s[nt][3] * scale : -INFINITY;
        }

        // ---- online softmax (per-row reduction over the 4-lane group) ----
        float mx0 = -INFINITY, mx1 = -INFINITY;
        #pragma unroll
        for (int nt = 0; nt < 8; nt++) {
            mx0 = fmaxf(mx0, fmaxf(s[nt][0], s[nt][1]));
            mx1 = fmaxf(mx1, fmaxf(s[nt][2], s[nt][3]));
        }
        mx0 = fmaxf(mx0, __shfl_xor_sync(0xffffffffu, mx0, 1));
        mx0 = fmaxf(mx0, __shfl_xor_sync(0xffffffffu, mx0, 2));
        mx1 = fmaxf(mx1, __shfl_xor_sync(0xffffffffu, mx1, 1));
        mx1 = fmaxf(mx1, __shfl_xor_sync(0xffffffffu, mx1, 2));

        const float mn0 = fmaxf(m0, mx0);
        const float mn1 = fmaxf(m1, mx1);
        const float al0 = __expf(m0 - mn0);   // 0 when m0 = -inf
        const float al1 = __expf(m1 - mn1);
        float rs0 = 0.f, rs1 = 0.f;
        #pragma unroll
        for (int nt = 0; nt < 8; nt++) {
            float p0 = __expf(s[nt][0] - mn0);
            float p1 = __expf(s[nt][1] - mn0);
            float p2 = __expf(s[nt][2] - mn1);
            float p3 = __expf(s[nt][3] - mn1);
            rs0 += p0 + p1;  rs1 += p2 + p3;
            s[nt][0] = p0; s[nt][1] = p1; s[nt][2] = p2; s[nt][3] = p3;
        }
        rs0 += __shfl_xor_sync(0xffffffffu, rs0, 1);
        rs0 += __shfl_xor_sync(0xffffffffu, rs0, 2);
        rs1 += __shfl_xor_sync(0xffffffffu, rs1, 1);
        rs1 += __shfl_xor_sync(0xffffffffu, rs1, 2);
        l0 = l0 * al0 + rs0;  m0 = mn0;
        l1 = l1 * al1 + rs1;  m1 = mn1;

        #pragma unroll
        for (int nt = 0; nt < 16; nt++) {
            o[nt][0] *= al0; o[nt][1] *= al0;
            o[nt][2] *= al1; o[nt][3] *= al1;
        }

        // ---- relayout P: C-frag -> smem -> A-frag (warp-private buffer) ----
        #pragma unroll
        for (int nt = 0; nt < 8; nt++) {
            const int c = nt * 8 + 2 * tr;
            Psw[g * PSTR + c]           = __uint_as_float(f2tf32(s[nt][0]));
            Psw[g * PSTR + c + 1]       = __uint_as_float(f2tf32(s[nt][1]));
            Psw[(g + 8) * PSTR + c]     = __uint_as_float(f2tf32(s[nt][2]));
            Psw[(g + 8) * PSTR + c + 1] = __uint_as_float(f2tf32(s[nt][3]));
        }
        __syncwarp();

        // ---- O += P V : 8 key-chunks x 16 n-tiles of m16n8k8 ----
        #pragma unroll
        for (int kc = 0; kc < 8; kc++) {
            const int kk0 = kc * 8;
            uint32_t a0 = __float_as_uint(Psw[g * PSTR + kk0 + tr]);
            uint32_t a1 = __float_as_uint(Psw[(g + 8) * PSTR + kk0 + tr]);
            uint32_t a2 = __float_as_uint(Psw[g * PSTR + kk0 + tr + 4]);
            uint32_t a3 = __float_as_uint(Psw[(g + 8) * PSTR + kk0 + tr + 4]);
            #pragma unroll
            for (int nt = 0; nt < 16; nt++) {
                uint32_t b0 = __float_as_uint(Vs[(kk0 + tr) * VSTR + nt * 8 + g]);
                uint32_t b1 = __float_as_uint(Vs[(kk0 + tr + 4) * VSTR + nt * 8 + g]);
                mma_tf32(o[nt], a0, a1, a2, a3, b0, b1);
            }
        }
        // next-iteration __syncthreads() orders PV reads before the next P store
    }

    // ---- epilogue: normalize, store (float2 per fragment pair) ----
    const float inv0 = 1.f / l0;
    const float inv1 = 1.f / l1;
    #pragma unroll
    for (int nt = 0; nt < 16; nt++) {
        const int c = nt * 8 + 2 * tr;
        float2 r0 = make_float2(o[nt][0] * inv0, o[nt][1] * inv0);
        float2 r1 = make_float2(o[nt][2] * inv1, o[nt][3] * inv1);
        *reinterpret_cast<float2*>(&ob[(size_t)qrow * CD + c]) = r0;
        *reinterpret_cast<float2*>(&ob[(size_t)(qrow + 8) * CD + c]) = r1;
    }
}

extern "C" void kernel_launch(void* const* d_in, const int* in_sizes, int n_in,
                              void* d_out, int out_size) {
    const float* q = (const float*)d_in[0];
    const float* k = (const float*)d_in[1];
    const float* v = (const float*)d_in[2];
    float* out = (float*)d_out;

    cudaFuncSetAttribute(swa_tf32_kernel,
                         cudaFuncAttributeMaxDynamicSharedMemorySize, SMEM_BYTES);

    dim3 grid(CL / BM, CB * CH);
    swa_tf32_kernel<<<grid, NTH, SMEM_BYTES>>>(q, k, v, out);
}

// round 4
// speedup vs baseline: 2.7017x; 1.4975x over previous
#include <cuda_runtime.h>
#include <math.h>
#include <stdint.h>

// Problem constants
#define CB 2
#define CH 16
#define CL 4096
#define CD 128
#define CWIN 2048
#define CSINK 4

#define BM 128           // queries per block (8 warps x 16 rows)
#define BN 64            // keys per tile
#define NTH 256
#define QSTR 132         // A-frag loads: bank = 4g+tr  (conflict-free)
#define KSTR 132         // B-frag loads: bank = 4g+tr  (conflict-free)
#define VSTR 136         // PV B-frag:    bank = 8tr+g  (conflict-free)
#define PSTR 68          // P A-frag:     bank = 4g+tr  (conflict-free)

#define SMEM_FLOATS (BM*QSTR + BN*KSTR + BN*VSTR + 8*16*PSTR)
#define SMEM_BYTES  (SMEM_FLOATS * 4)   // 171008 B

__device__ __forceinline__ uint32_t f2tf32(float x) {
    uint32_t r;
    asm("cvt.rna.tf32.f32 %0, %1;" : "=r"(r) : "f"(x));
    return r;
}

__device__ __forceinline__ void mma_tf32(float c[4],
                                         uint32_t a0, uint32_t a1, uint32_t a2, uint32_t a3,
                                         uint32_t b0, uint32_t b1) {
    asm volatile(
        "mma.sync.aligned.m16n8k8.row.col.f32.tf32.tf32.f32 "
        "{%0,%1,%2,%3}, {%4,%5,%6,%7}, {%8,%9}, {%0,%1,%2,%3};"
        : "+f"(c[0]), "+f"(c[1]), "+f"(c[2]), "+f"(c[3])
        : "r"(a0), "r"(a1), "r"(a2), "r"(a3), "r"(b0), "r"(b1));
}

__global__ __launch_bounds__(NTH, 1)
void swa_tf32_kernel(const float* __restrict__ Q, const float* __restrict__ K,
                     const float* __restrict__ V, float* __restrict__ O) {
    extern __shared__ float sm[];
    float* Qs = sm;                       // BM x QSTR
    float* Ks = Qs + BM * QSTR;           // BN x KSTR
    float* Vs = Ks + BN * KSTR;           // BN x VSTR
    float* Ps = Vs + BN * VSTR;           // 8 warps x 16 x PSTR

    const int bh  = blockIdx.y;
    const int q0  = blockIdx.x * BM;
    const int tid = threadIdx.x;
    const int wid = tid >> 5;
    const int lane = tid & 31;
    const int g   = lane >> 2;            // groupID (0..7)
    const int tr  = lane & 3;             // thread-in-group (0..3)
    const float scale = 0.08838834764831843f;   // 1/sqrt(128)

    const size_t base = (size_t)bh * CL * CD;
    const float* qb = Q + base + (size_t)q0 * CD;
    const float* kb = K + base;
    const float* vb = V + base;
    float*       ob = O + base + (size_t)q0 * CD;

    // ---- load Q tile (cvt to tf32 bits once) ----
    for (int e = tid; e < BM * CD / 4; e += NTH) {
        const int r = e >> 5, c = (e & 31) << 2;
        float4 qv = reinterpret_cast<const float4*>(qb)[e];
        float* dst = &Qs[r * QSTR + c];
        dst[0] = __uint_as_float(f2tf32(qv.x));
        dst[1] = __uint_as_float(f2tf32(qv.y));
        dst[2] = __uint_as_float(f2tf32(qv.z));
        dst[3] = __uint_as_float(f2tf32(qv.w));
    }

    // ---- per-thread state ----
    float m0 = -INFINITY, m1 = -INFINITY, l0 = 0.f, l1 = 0.f;
    float o[16][4];
    #pragma unroll
    for (int nt = 0; nt < 16; nt++) {
        o[nt][0] = 0.f; o[nt][1] = 0.f; o[nt][2] = 0.f; o[nt][3] = 0.f;
    }

    float* Psw = Ps + wid * 16 * PSTR;
    const int qrow = wid * 16 + g;
    const int qp0 = q0 + qrow, qp1 = qp0 + 8;
    const int wq0 = q0 + wid * 16;        // warp's smallest query pos
    const int wq1 = wq0 + 15;             // warp's largest query pos

    // ---- k-tile schedule: sink tile 0 (if disjoint) then window band ----
    // band covers window of smallest query .. causal frontier of largest query
    const int kt_hi = (q0 + BM - 1) >> 6;
    const int kt_lo = (q0 >= CWIN) ? ((q0 - CWIN + 1) >> 6) : 0;
    const int ntiles = kt_hi - kt_lo + 1 + (kt_lo > 0 ? 1 : 0);

    for (int t = 0; t < ntiles; t++) {
        const int kt = (kt_lo > 0) ? (t == 0 ? 0 : kt_lo + t - 1) : t;
        const int k0 = kt * BN;
        const bool sink_only = (kt_lo > 0) && (t == 0);

        __syncthreads();   // previous iter done with Ks/Vs (and Ps)
        // ---- load K, V tiles (cvt to tf32 bits) ----
        for (int e = tid; e < BN * CD / 4; e += NTH) {
            const int r = e >> 5, c = (e & 31) << 2;
            float4 kk = reinterpret_cast<const float4*>(kb + (size_t)k0 * CD)[e];
            float4 vv = reinterpret_cast<const float4*>(vb + (size_t)k0 * CD)[e];
            float* kd = &Ks[r * KSTR + c];
            kd[0] = __uint_as_float(f2tf32(kk.x));
            kd[1] = __uint_as_float(f2tf32(kk.y));
            kd[2] = __uint_as_float(f2tf32(kk.z));
            kd[3] = __uint_as_float(f2tf32(kk.w));
            float* vd = &Vs[r * VSTR + c];
            vd[0] = __uint_as_float(f2tf32(vv.x));
            vd[1] = __uint_as_float(f2tf32(vv.y));
            vd[2] = __uint_as_float(f2tf32(vv.z));
            vd[3] = __uint_as_float(f2tf32(vv.w));
        }
        __syncthreads();

        // ---- whole-tile skip for this warp (warp-uniform) ----
        // live iff some key in [k0,k0+63] can be attended by some row in [wq0,wq1]
        const bool warp_live =
            (k0 <= wq1) && ((k0 + BN - 1 + CWIN > wq0) || (k0 < CSINK));
        if (warp_live) {
            // ---- S = Q K^T ----
            float s[8][4];
            #pragma unroll
            for (int nt = 0; nt < 8; nt++) {
                s[nt][0] = 0.f; s[nt][1] = 0.f; s[nt][2] = 0.f; s[nt][3] = 0.f;
            }
            #pragma unroll
            for (int kc = 0; kc < 16; kc++) {
                const int d0 = kc * 8;
                uint32_t a0 = __float_as_uint(Qs[qrow * QSTR + d0 + tr]);
                uint32_t a1 = __float_as_uint(Qs[(qrow + 8) * QSTR + d0 + tr]);
                uint32_t a2 = __float_as_uint(Qs[qrow * QSTR + d0 + tr + 4]);
                uint32_t a3 = __float_as_uint(Qs[(qrow + 8) * QSTR + d0 + tr + 4]);
                {   // nt = 0 always computed
                    uint32_t b0 = __float_as_uint(Ks[g * KSTR + d0 + tr]);
                    uint32_t b1 = __float_as_uint(Ks[g * KSTR + d0 + tr + 4]);
                    mma_tf32(s[0], a0, a1, a2, a3, b0, b1);
                }
                if (!sink_only) {
                    #pragma unroll
                    for (int nt = 1; nt < 8; nt++) {
                        uint32_t b0 = __float_as_uint(Ks[(nt * 8 + g) * KSTR + d0 + tr]);
                        uint32_t b1 = __float_as_uint(Ks[(nt * 8 + g) * KSTR + d0 + tr + 4]);
                        mma_tf32(s[nt], a0, a1, a2, a3, b0, b1);
                    }
                }
            }

            // ---- mask + scale (exact per-element) ----
            #pragma unroll
            for (int nt = 0; nt < 8; nt++) {
                const int kpa = k0 + nt * 8 + 2 * tr;
                const int kpb = kpa + 1;
                const bool sa = kpa < CSINK, sb = kpb < CSINK;
                const bool ok00 = (kpa <= qp0) && ((kpa + CWIN > qp0) || sa);
                const bool ok01 = (kpb <= qp0) && ((kpb + CWIN > qp0) || sb);
                const bool ok10 = (kpa <= qp1) && ((kpa + CWIN > qp1) || sa);
                const bool ok11 = (kpb <= qp1) && ((kpb + CWIN > qp1) || sb);
                s[nt][0] = ok00 ? s[nt][0] * scale : -INFINITY;
                s[nt][1] = ok01 ? s[nt][1] * scale : -INFINITY;
                s[nt][2] = ok10 ? s[nt][2] * scale : -INFINITY;
                s[nt][3] = ok11 ? s[nt][3] * scale : -INFINITY;
            }

            // ---- online softmax ----
            float mx0 = -INFINITY, mx1 = -INFINITY;
            #pragma unroll
            for (int nt = 0; nt < 8; nt++) {
                mx0 = fmaxf(mx0, fmaxf(s[nt][0], s[nt][1]));
                mx1 = fmaxf(mx1, fmaxf(s[nt][2], s[nt][3]));
            }
            mx0 = fmaxf(mx0, __shfl_xor_sync(0xffffffffu, mx0, 1));
            mx0 = fmaxf(mx0, __shfl_xor_sync(0xffffffffu, mx0, 2));
            mx1 = fmaxf(mx1, __shfl_xor_sync(0xffffffffu, mx1, 1));
            mx1 = fmaxf(mx1, __shfl_xor_sync(0xffffffffu, mx1, 2));

            const float mn0 = fmaxf(m0, mx0);
            const float mn1 = fmaxf(m1, mx1);
            const float al0 = __expf(m0 - mn0);   // first live tile: every row has
            const float al1 = __expf(m1 - mn1);   // a valid sink/causal col -> mn finite
            float rs0 = 0.f, rs1 = 0.f;
            #pragma unroll
            for (int nt = 0; nt < 8; nt++) {
                float p0 = __expf(s[nt][0] - mn0);
                float p1 = __expf(s[nt][1] - mn0);
                float p2 = __expf(s[nt][2] - mn1);
                float p3 = __expf(s[nt][3] - mn1);
                rs0 += p0 + p1;  rs1 += p2 + p3;
                s[nt][0] = p0; s[nt][1] = p1; s[nt][2] = p2; s[nt][3] = p3;
            }
            rs0 += __shfl_xor_sync(0xffffffffu, rs0, 1);
            rs0 += __shfl_xor_sync(0xffffffffu, rs0, 2);
            rs1 += __shfl_xor_sync(0xffffffffu, rs1, 1);
            rs1 += __shfl_xor_sync(0xffffffffu, rs1, 2);
            l0 = l0 * al0 + rs0;  m0 = mn0;
            l1 = l1 * al1 + rs1;  m1 = mn1;

            #pragma unroll
            for (int nt = 0; nt < 16; nt++) {
                o[nt][0] *= al0; o[nt][1] *= al0;
                o[nt][2] *= al1; o[nt][3] *= al1;
            }

            // ---- relayout P: C-frag -> smem -> A-frag (warp-private) ----
            #pragma unroll
            for (int nt = 0; nt < 8; nt++) {
                const int c = nt * 8 + 2 * tr;
                Psw[g * PSTR + c]           = __uint_as_float(f2tf32(s[nt][0]));
                Psw[g * PSTR + c + 1]       = __uint_as_float(f2tf32(s[nt][1]));
                Psw[(g + 8) * PSTR + c]     = __uint_as_float(f2tf32(s[nt][2]));
                Psw[(g + 8) * PSTR + c + 1] = __uint_as_float(f2tf32(s[nt][3]));
            }
            __syncwarp();

            // ---- PV key-chunk range (warp-uniform) ----
            int kchi = (wq1 - k0) >> 3;               // causal frontier
            if (kchi > 7) kchi = 7;
            const int lo_raw = wq0 - CWIN - 6 - k0;   // window tail
            int kclo = lo_raw > 0 ? ((lo_raw + 7) >> 3) : 0;
            if (k0 == 0) kclo = 0;                    // sinks live in tile 0
            if (sink_only) kchi = 0;                  // only keys 0..7 useful

            // ---- O += P V ----
            #pragma unroll
            for (int kc = 0; kc < 8; kc++) {
                if (kc >= kclo && kc <= kchi) {
                    const int kk0 = kc * 8;
                    uint32_t a0 = __float_as_uint(Psw[g * PSTR + kk0 + tr]);
                    uint32_t a1 = __float_as_uint(Psw[(g + 8) * PSTR + kk0 + tr]);
                    uint32_t a2 = __float_as_uint(Psw[g * PSTR + kk0 + tr + 4]);
                    uint32_t a3 = __float_as_uint(Psw[(g + 8) * PSTR + kk0 + tr + 4]);
                    #pragma unroll
                    for (int nt = 0; nt < 16; nt++) {
                        uint32_t b0 = __float_as_uint(Vs[(kk0 + tr) * VSTR + nt * 8 + g]);
                        uint32_t b1 = __float_as_uint(Vs[(kk0 + tr + 4) * VSTR + nt * 8 + g]);
                        mma_tf32(o[nt], a0, a1, a2, a3, b0, b1);
                    }
                }
            }
        }
        // next-iteration __syncthreads() orders PV/K/V reads before overwrite
    }

    // ---- epilogue: normalize, store ----
    const float inv0 = 1.f / l0;
    const float inv1 = 1.f / l1;
    #pragma unroll
    for (int nt = 0; nt < 16; nt++) {
        const int c = nt * 8 + 2 * tr;
        float2 r0 = make_float2(o[nt][0] * inv0, o[nt][1] * inv0);
        float2 r1 = make_float2(o[nt][2] * inv1, o[nt][3] * inv1);
        *reinterpret_cast<float2*>(&ob[(size_t)qrow * CD + c]) = r0;
        *reinterpret_cast<float2*>(&ob[(size_t)(qrow + 8) * CD + c]) = r1;
    }
}

extern "C" void kernel_launch(void* const* d_in, const int* in_sizes, int n_in,
                              void* d_out, int out_size) {
    const float* q = (const float*)d_in[0];
    const float* k = (const float*)d_in[1];
    const float* v = (const float*)d_in[2];
    float* out = (float*)d_out;

    cudaFuncSetAttribute(swa_tf32_kernel,
                         cudaFuncAttributeMaxDynamicSharedMemorySize, SMEM_BYTES);

    dim3 grid(CL / BM, CB * CH);
    swa_tf32_kernel<<<grid, NTH, SMEM_BYTES>>>(q, k, v, out);
}